// round 1
// baseline (speedup 1.0000x reference)
#include <cuda_runtime.h>
#include <cuda_bf16.h>
#include <cstdint>

// MaxUnpooling2D scatter-add.
// inputs:  d_in[0] float32, (B=8, H=128, W=128, C=256)  -> 33,554,432 elems
// indices: d_in[1] int32, same shape, values in [0, Ho*Wo*C) = [0, 16,777,216)
// output:  float32, (B=8, 256, 256, 256) = 134,217,728 elems, zero-init, scatter-SUM.

static constexpr int ELEMS_PER_BATCH_IN  = 128 * 128 * 256;   // 2^22
static constexpr int ELEMS_PER_BATCH_OUT = 256 * 256 * 256;   // 2^24
static constexpr int N_IN = 8 * ELEMS_PER_BATCH_IN;           // 2^25

__global__ void __launch_bounds__(256)
unpool_scatter_kernel(const float4* __restrict__ vals4,
                      const int4*  __restrict__ idx4,
                      float* __restrict__ out)
{
    int n4 = N_IN / 4;  // 8,388,608 vec4 elements
    int stride = gridDim.x * blockDim.x;
    for (int i = blockIdx.x * blockDim.x + threadIdx.x; i < n4; i += stride) {
        float4 v = vals4[i];
        int4   x = idx4[i];
        // scalar element index of first lane of this vec4
        int e = i << 2;
        // batch = e >> 22 ; all 4 elements of a vec4 share the same batch
        // (ELEMS_PER_BATCH_IN = 2^22 is divisible by 4)
        int base = (e >> 22) << 24;  // batch * 2^24
        atomicAdd(out + (base + x.x), v.x);
        atomicAdd(out + (base + x.y), v.y);
        atomicAdd(out + (base + x.z), v.z);
        atomicAdd(out + (base + x.w), v.w);
    }
}

extern "C" void kernel_launch(void* const* d_in, const int* in_sizes, int n_in,
                              void* d_out, int out_size)
{
    const float4* vals = (const float4*)d_in[0];
    const int4*   idx  = (const int4*)d_in[1];
    float* out = (float*)d_out;

    // Zero-fill the output (memset node is graph-capturable).
    cudaMemsetAsync(d_out, 0, (size_t)out_size * sizeof(float));

    int n4 = N_IN / 4;
    int threads = 256;
    int blocks = (n4 + threads - 1) / threads;  // 32768 blocks -> many waves, fine
    unpool_scatter_kernel<<<blocks, threads>>>(vals, idx, out);
}

// round 2
// speedup vs baseline: 1.8415x; 1.8415x over previous
#include <cuda_runtime.h>
#include <cuda_bf16.h>
#include <cstdint>

// MaxUnpooling2D scatter-add, batch-by-batch so each 64MB output slice stays
// resident in the 126MB L2 between its zero-fill and its atomic scatter.
//
// inputs:  d_in[0] float32, (B=8, 128, 128, 256)  -> 2^25 elems total
// indices: d_in[1] int32, same shape, values in [0, 2^24)
// output:  float32, (8, 256, 256, 256) = 2^27 elems, zero-init, scatter-SUM.

static constexpr int B          = 8;
static constexpr int IN_PER_B   = 1 << 22;   // 4,194,304 elems  (16 MB f32)
static constexpr int OUT_PER_B  = 1 << 24;   // 16,777,216 elems (64 MB f32)

// ---------------------------------------------------------------------------
// Zero one batch's output slice with wide stores (allocates dirty L2 lines).
// OUT_PER_B/4 = 4,194,304 float4 -> 16384 blocks x 256 threads, no loop.
// ---------------------------------------------------------------------------
__global__ void __launch_bounds__(256)
zero_batch_kernel(float4* __restrict__ out4)
{
    int i = blockIdx.x * blockDim.x + threadIdx.x;
    out4[i] = make_float4(0.f, 0.f, 0.f, 0.f);
}

// ---------------------------------------------------------------------------
// Scatter one batch: 2^20 vec4 iterations -> 4096 blocks x 256 threads.
// Input/index loads are evict-first streaming (__ldcs) so the output slice
// keeps its L2 residency; atomicAdd with unused return compiles to RED.
// ---------------------------------------------------------------------------
__global__ void __launch_bounds__(256)
scatter_batch_kernel(const float4* __restrict__ vals4,
                     const int4*  __restrict__ idx4,
                     float* __restrict__ out)
{
    int i = blockIdx.x * blockDim.x + threadIdx.x;
    float4 v = __ldcs(vals4 + i);
    int4   x = __ldcs(idx4 + i);
    atomicAdd(out + x.x, v.x);
    atomicAdd(out + x.y, v.y);
    atomicAdd(out + x.z, v.z);
    atomicAdd(out + x.w, v.w);
}

extern "C" void kernel_launch(void* const* d_in, const int* in_sizes, int n_in,
                              void* d_out, int out_size)
{
    const float* vals = (const float*)d_in[0];
    const int*   idx  = (const int*)d_in[1];
    float* out = (float*)d_out;

    const int zero_blocks    = (OUT_PER_B / 4) / 256;  // 16384
    const int scatter_blocks = (IN_PER_B  / 4) / 256;  // 4096

    for (int b = 0; b < B; b++) {
        float4* out4_b = (float4*)(out + (size_t)b * OUT_PER_B);
        zero_batch_kernel<<<zero_blocks, 256>>>(out4_b);
        scatter_batch_kernel<<<scatter_blocks, 256>>>(
            (const float4*)(vals + (size_t)b * IN_PER_B),
            (const int4*)(idx + (size_t)b * IN_PER_B),
            out + (size_t)b * OUT_PER_B);
    }
}